// round 7
// baseline (speedup 1.0000x reference)
#include <cuda_runtime.h>

#define BB 4
#define LL 512
#define DD 128
#define BL (BB*LL)
#define TI 4
#define CH 32          // j rows per staged chunk

// Scratch (device globals; no allocation)
__device__ float g_E[BL*DD];                 // exp2(2*log2e * (inp @ Wu^T))  indexed by j
__device__ float g_F[BL*DD];                 // exp2(2*log2e * (inp @ Ww^T))  indexed by i
__device__ float g_attn_scratch[BB*LL*LL];   // used only if harness doesn't want attn

__device__ __forceinline__ float ex2a(float x){ float y; asm("ex2.approx.ftz.f32 %0, %1;" : "=f"(y) : "f"(x)); return y; }
__device__ __forceinline__ float rcpa(float x){ float y; asm("rcp.approx.ftz.f32 %0, %1;" : "=f"(y) : "f"(x)); return y; }

// ---------------------------------------------------------------------------
// Kernel A: qu = inp @ Wu^T, kw = inp @ Ww^T ; store E=exp2(K*qu), F=exp2(K*kw)
// ---------------------------------------------------------------------------
__global__ __launch_bounds__(128) void proj_kernel(const float* __restrict__ inp,
                                                   const float* __restrict__ Wu,
                                                   const float* __restrict__ Ww){
    __shared__ __align__(16) float sW[128*33];
    __shared__ __align__(16) float sI[16*33];
    const float* W  = blockIdx.y ? Ww  : Wu;
    float*       dst = blockIdx.y ? g_F : g_E;
    const int r0  = blockIdx.x * 16;
    const int tid = threadIdx.x;

    float acc[16];
    #pragma unroll
    for (int r = 0; r < 16; r++) acc[r] = 0.f;

    for (int dc = 0; dc < 128; dc += 32){
        for (int idx = tid; idx < 128*32; idx += 128){
            int t = idx >> 5, c = idx & 31;
            sW[t*33 + c] = W[t*128 + dc + c];
        }
        for (int idx = tid; idx < 16*32; idx += 128){
            int r = idx >> 5, c = idx & 31;
            sI[r*33 + c] = inp[(r0 + r)*128 + dc + c];
        }
        __syncthreads();
        #pragma unroll 8
        for (int c = 0; c < 32; c++){
            float w = sW[tid*33 + c];
            #pragma unroll
            for (int r = 0; r < 16; r++) acc[r] += sI[r*33 + c] * w;
        }
        __syncthreads();
    }
    const float K = 2.8853900817779268f;  // 2*log2(e)
    #pragma unroll
    for (int r = 0; r < 16; r++)
        dst[(r0 + r)*128 + tid] = ex2a(K * acc[r]);
}

// ---------------------------------------------------------------------------
// Kernel B: fused scores + softmax + attn write + out = attn @ inp
// grid 512, block 256, 4 blocks/SM.
// score[i][j] = Cwv - 2 * sum_d wv[d] * rcp(1 + E[j,d]*F[i,d])
// Score lane map: jg = lane&3 (j within warp quad), dq = lane>>2 (16-wide d group).
// Cross-dq reduction via shfl_xor(4,8,16) — no smem partials, 2 barriers/chunk.
// ---------------------------------------------------------------------------
__global__ __launch_bounds__(256, 4) void attn_kernel(const float* __restrict__ inp,
                                                      const float* __restrict__ wvp,
                                                      float* __restrict__ out,
                                                      float* __restrict__ attn){
    __shared__ __align__(16) float sE [CH*132];     // E / inp chunk (pad 132)
    __shared__ __align__(16) float sF [TI*128];
    __shared__ __align__(16) float swv[128];
    __shared__ __align__(16) float ss [TI*512];     // scores -> attn row cache
    __shared__ __align__(16) float sp2[2*TI*128];   // bmm partials per j-half
    const int tid  = threadIdx.x;
    const int b    = blockIdx.x >> 7;               // /128
    const int i0   = (blockIdx.x & 127) * TI;
    const int lane = tid & 31;
    const int warp = tid >> 5;

    if (tid < 128) swv[tid] = wvp[tid];
    for (int idx = tid; idx < TI*128; idx += 256)
        sF[idx] = g_F[(b*LL + i0 + (idx >> 7))*128 + (idx & 127)];
    __syncthreads();

    // cw = sum(wv) via shuffle reduction
    float cw = swv[lane] + swv[lane+32] + swv[lane+64] + swv[lane+96];
    #pragma unroll
    for (int o = 16; o > 0; o >>= 1) cw += __shfl_xor_sync(0xffffffffu, cw, o);

    const int jg    = lane & 3;        // j within warp's quad
    const int dq    = lane >> 2;       // d-group (0..7), 16 d each
    const int dbase = dq * 16;
    const int jrow  = warp * 4 + jg;   // j within chunk (0..31)

    // wv slice held in registers for the whole score phase
    const float4 w0 = *(const float4*)&swv[dbase +  0];
    const float4 w1 = *(const float4*)&swv[dbase +  4];
    const float4 w2 = *(const float4*)&swv[dbase +  8];
    const float4 w3 = *(const float4*)&swv[dbase + 12];

    // ---------------- scores ----------------
    #pragma unroll 1
    for (int ch = 0; ch < LL/CH; ch++){
        const int j0 = ch * CH;
        #pragma unroll
        for (int idx = tid; idx < CH*32; idx += 256){
            int r = idx >> 5, c = idx & 31;
            *(float4*)&sE[r*132 + c*4] =
                *(const float4*)&g_E[(b*LL + j0 + r)*128 + c*4];
        }
        __syncthreads();

        const float* Er = &sE[jrow*132 + dbase];
        float4 e0 = *(const float4*)(Er +  0);
        float4 e1 = *(const float4*)(Er +  4);
        float4 e2 = *(const float4*)(Er +  8);
        float4 e3 = *(const float4*)(Er + 12);

        #pragma unroll 1
        for (int i = 0; i < TI; i++){
            const float* Fr = &sF[i*128 + dbase];
            float4 f0 = *(const float4*)(Fr +  0);
            float4 f1 = *(const float4*)(Fr +  4);
            float4 f2 = *(const float4*)(Fr +  8);
            float4 f3 = *(const float4*)(Fr + 12);
            // 4 independent accumulator chains over 16 d
            float a0 = w0.x * rcpa(fmaf(e0.x, f0.x, 1.f));
            float a1 = w0.y * rcpa(fmaf(e0.y, f0.y, 1.f));
            float a2 = w0.z * rcpa(fmaf(e0.z, f0.z, 1.f));
            float a3 = w0.w * rcpa(fmaf(e0.w, f0.w, 1.f));
            a0 = fmaf(w1.x, rcpa(fmaf(e1.x, f1.x, 1.f)), a0);
            a1 = fmaf(w1.y, rcpa(fmaf(e1.y, f1.y, 1.f)), a1);
            a2 = fmaf(w1.z, rcpa(fmaf(e1.z, f1.z, 1.f)), a2);
            a3 = fmaf(w1.w, rcpa(fmaf(e1.w, f1.w, 1.f)), a3);
            a0 = fmaf(w2.x, rcpa(fmaf(e2.x, f2.x, 1.f)), a0);
            a1 = fmaf(w2.y, rcpa(fmaf(e2.y, f2.y, 1.f)), a1);
            a2 = fmaf(w2.z, rcpa(fmaf(e2.z, f2.z, 1.f)), a2);
            a3 = fmaf(w2.w, rcpa(fmaf(e2.w, f2.w, 1.f)), a3);
            a0 = fmaf(w3.x, rcpa(fmaf(e3.x, f3.x, 1.f)), a0);
            a1 = fmaf(w3.y, rcpa(fmaf(e3.y, f3.y, 1.f)), a1);
            a2 = fmaf(w3.z, rcpa(fmaf(e3.z, f3.z, 1.f)), a2);
            a3 = fmaf(w3.w, rcpa(fmaf(e3.w, f3.w, 1.f)), a3);
            float s = (a0 + a1) + (a2 + a3);
            // reduce across the 8 dq lanes (bits 2..4 of lane id)
            s += __shfl_xor_sync(0xffffffffu, s, 4);
            s += __shfl_xor_sync(0xffffffffu, s, 8);
            s += __shfl_xor_sync(0xffffffffu, s, 16);
            if (dq == 0) ss[i*512 + j0 + jrow] = cw - 2.f * s;
        }
        __syncthreads();
    }

    // ---------------- softmax over j (one warp per i) ----------------
    if (warp < TI){
        float m = -1e30f;
        #pragma unroll
        for (int k = 0; k < 16; k++) m = fmaxf(m, ss[warp*512 + lane + k*32]);
        #pragma unroll
        for (int o = 16; o > 0; o >>= 1) m = fmaxf(m, __shfl_xor_sync(0xffffffffu, m, o));
        const float L2E = 1.4426950408889634f;
        float sum = 0.f;
        #pragma unroll
        for (int k = 0; k < 16; k++){
            float e = ex2a((ss[warp*512 + lane + k*32] - m) * L2E);
            ss[warp*512 + lane + k*32] = e;
            sum += e;
        }
        #pragma unroll
        for (int o = 16; o > 0; o >>= 1) sum += __shfl_xor_sync(0xffffffffu, sum, o);
        float inv = 1.0f / sum;   // accurate div, only 2048 total
        #pragma unroll
        for (int k = 0; k < 16; k++){
            float a = ss[warp*512 + lane + k*32] * inv;
            ss[warp*512 + lane + k*32] = a;
            attn[(b*LL + i0 + warp)*LL + lane + k*32] = a;
        }
    }
    __syncthreads();

    // ---------------- out = attn @ inp ----------------
    // Thread owns one d, computes all TI rows from each staged value (v reused x4).
    // h = tid>>7 splits the j range of each chunk in half; partials combined in smem.
    const int d = tid & 127, h = tid >> 7;
    float b0 = 0.f, b1 = 0.f, b2 = 0.f, b3 = 0.f;
    #pragma unroll 1
    for (int ch = 0; ch < LL/CH; ch++){
        const int j0 = ch * CH;
        #pragma unroll
        for (int idx = tid; idx < CH*32; idx += 256){
            int r = idx >> 5, c = idx & 31;
            *(float4*)&sE[r*132 + c*4] =
                *(const float4*)&inp[(b*LL + j0 + r)*128 + c*4];
        }
        __syncthreads();
        const int jb = h * 16;
        #pragma unroll
        for (int jj = 0; jj < 16; jj++){
            float v = sE[(jb + jj)*132 + d];
            b0 = fmaf(ss[0*512 + j0 + jb + jj], v, b0);
            b1 = fmaf(ss[1*512 + j0 + jb + jj], v, b1);
            b2 = fmaf(ss[2*512 + j0 + jb + jj], v, b2);
            b3 = fmaf(ss[3*512 + j0 + jb + jj], v, b3);
        }
        __syncthreads();
    }
    sp2[(h*TI + 0)*128 + d] = b0;
    sp2[(h*TI + 1)*128 + d] = b1;
    sp2[(h*TI + 2)*128 + d] = b2;
    sp2[(h*TI + 3)*128 + d] = b3;
    __syncthreads();
    #pragma unroll
    for (int idx = tid; idx < TI*128; idx += 256){
        int i = idx >> 7, dd = idx & 127;
        out[(b*LL + i0 + i)*128 + dd] = sp2[i*128 + dd] + sp2[(TI + i)*128 + dd];
    }
}

// ---------------------------------------------------------------------------
extern "C" void kernel_launch(void* const* d_in, const int* in_sizes, int n_in,
                              void* d_out, int out_size){
    const float* inp = (const float*)d_in[0];
    const float* Wu  = (const float*)d_in[1];
    const float* Ww  = (const float*)d_in[2];
    const float* Wv  = (const float*)d_in[3];
    float* out = (float*)d_out;

    float* attn;
    if (out_size >= BB*LL*DD + BB*LL*LL){
        attn = out + BB*LL*DD;               // tuple layout: [out | attn]
    } else {
        void* p = nullptr;
        cudaGetSymbolAddress(&p, g_attn_scratch);
        attn = (float*)p;
    }

    proj_kernel<<<dim3(BL/16, 2), 128>>>(inp, Wu, Ww);
    attn_kernel<<<BL/TI, 256>>>(inp, Wv, out, attn);
}

// round 10
// speedup vs baseline: 1.1317x; 1.1317x over previous
#include <cuda_runtime.h>
#include <cstdint>

#define BB 4
#define LL 512
#define DD 128
#define BL (BB*LL)
#define TI 4
#define CH 32          // j rows per staged chunk
#define NCHUNK (LL/CH) // 16

// Scratch (device globals; no allocation)
__device__ float g_E[BL*DD];                 // exp2(2*log2e * (inp @ Wu^T))  indexed by j
__device__ float g_F[BL*DD];                 // exp2(2*log2e * (inp @ Ww^T))  indexed by i
__device__ float g_attn_scratch[BB*LL*LL];   // used only if harness doesn't want attn

__device__ __forceinline__ float ex2a(float x){ float y; asm("ex2.approx.ftz.f32 %0, %1;" : "=f"(y) : "f"(x)); return y; }
__device__ __forceinline__ float rcpa(float x){ float y; asm("rcp.approx.ftz.f32 %0, %1;" : "=f"(y) : "f"(x)); return y; }
__device__ __forceinline__ uint32_t s2u(const void* p){ return (uint32_t)__cvta_generic_to_shared(p); }

#define CPASYNC16(dst, src) asm volatile("cp.async.cg.shared.global [%0], [%1], 16;" :: "r"(dst), "l"(src) : "memory")
#define CPCOMMIT()          asm volatile("cp.async.commit_group;" ::: "memory")
#define CPWAIT0()           asm volatile("cp.async.wait_group 0;" ::: "memory")

// ---------------------------------------------------------------------------
// Kernel A: qu = inp @ Wu^T, kw = inp @ Ww^T ; store E=exp2(K*qu), F=exp2(K*kw)
// 8-row tiles -> grid (BL/8, 2) = 512 blocks for SM coverage.
// ---------------------------------------------------------------------------
__global__ __launch_bounds__(128) void proj_kernel(const float* __restrict__ inp,
                                                   const float* __restrict__ Wu,
                                                   const float* __restrict__ Ww){
    __shared__ __align__(16) float sW[128*33];
    __shared__ __align__(16) float sI[8*33];
    const float* W  = blockIdx.y ? Ww  : Wu;
    float*       dst = blockIdx.y ? g_F : g_E;
    const int r0  = blockIdx.x * 8;
    const int tid = threadIdx.x;

    float acc[8];
    #pragma unroll
    for (int r = 0; r < 8; r++) acc[r] = 0.f;

    for (int dc = 0; dc < 128; dc += 32){
        for (int idx = tid; idx < 128*32; idx += 128){
            int t = idx >> 5, c = idx & 31;
            sW[t*33 + c] = W[t*128 + dc + c];
        }
        for (int idx = tid; idx < 8*32; idx += 128){
            int r = idx >> 5, c = idx & 31;
            sI[r*33 + c] = inp[(r0 + r)*128 + dc + c];
        }
        __syncthreads();
        #pragma unroll 8
        for (int c = 0; c < 32; c++){
            float w = sW[tid*33 + c];            // stride-33 -> conflict-free
            #pragma unroll
            for (int r = 0; r < 8; r++) acc[r] += sI[r*33 + c] * w;   // broadcast
        }
        __syncthreads();
    }
    const float K = 2.8853900817779268f;  // 2*log2(e)
    #pragma unroll
    for (int r = 0; r < 8; r++)
        dst[(r0 + r)*128 + tid] = ex2a(K * acc[r]);
}

// ---------------------------------------------------------------------------
// Kernel B: fused scores + softmax + attn write + out = attn @ inp
// grid 512, block 256, 4 blocks/SM.
// score[i][j] = cw - 2 * sum_d wv[d]*rcp(1+E[j,d]F[i,d])
// Pair trick: with q=1/w, A' = q0*(1+e0*F0) = fmaf(e0, F0*q0, q0):
//   w0/A + w1/B = (A'+B')*rcp(A'*B')   -> 1 MUFU per 2 elements.
// Lane map: jg = lane&1 (j), dq = lane>>1 (8-wide d group). F*q held in regs.
// ---------------------------------------------------------------------------
__global__ __launch_bounds__(256, 4) void attn_kernel(const float* __restrict__ inp,
                                                      const float* __restrict__ wvp,
                                                      float* __restrict__ out,
                                                      float* __restrict__ attn){
    __shared__ __align__(16) float sE [2][CH*132];  // double-buffered E/inp chunk
    __shared__ __align__(16) float sF [TI*128];
    __shared__ __align__(16) float swv[128];
    __shared__ __align__(16) float ss [TI*512];     // scores -> attn row cache
    __shared__ __align__(16) float sp2[2*TI*128];   // bmm partials per j-half
    const int tid  = threadIdx.x;
    const int b    = blockIdx.x >> 7;               // /128
    const int i0   = (blockIdx.x & 127) * TI;
    const int lane = tid & 31;
    const int warp = tid >> 5;

    if (tid < 128) swv[tid] = wvp[tid];
    for (int idx = tid; idx < TI*128; idx += 256)
        sF[idx] = g_F[(b*LL + i0 + (idx >> 7))*128 + (idx & 127)];
    __syncthreads();

    // cw = sum(wv) via shuffle reduction
    float cw = swv[lane] + swv[lane+32] + swv[lane+64] + swv[lane+96];
    #pragma unroll
    for (int o = 16; o > 0; o >>= 1) cw += __shfl_xor_sync(0xffffffffu, cw, o);

    const int jg    = lane & 1;        // j within warp pair
    const int dq    = lane >> 1;       // d-group (0..15), 8 d each
    const int dbase = dq * 8;
    const int jbase = warp * 2 + jg;   // j within 16-row pass

    // q = 1/wv and Fq = F*q held in registers for the whole score phase
    float qv[8];
    #pragma unroll
    for (int k = 0; k < 8; k++) qv[k] = 1.0f / swv[dbase + k];
    float Fq[TI][8];
    #pragma unroll
    for (int i = 0; i < TI; i++)
        #pragma unroll
        for (int k = 0; k < 8; k++) Fq[i][k] = sF[i*128 + dbase + k] * qv[k];

    const float* gE = &g_E[b*LL*DD];
    const int sr = tid >> 5, sc = (tid & 31) * 4;   // staging row/col (4 rows apart x4)

    // stage chunk 0 into buffer 0
    #pragma unroll
    for (int t = 0; t < 4; t++)
        CPASYNC16(s2u(&sE[0][(sr + t*8)*132 + sc]), &gE[(sr + t*8)*128 + sc]);
    CPCOMMIT(); CPWAIT0();
    __syncthreads();

    // ---------------- scores ----------------
    #pragma unroll 1
    for (int ch = 0; ch < NCHUNK; ch++){
        const int cur = ch & 1;
        if (ch < NCHUNK-1){
            const float* src = &gE[(ch+1)*CH*128];
            #pragma unroll
            for (int t = 0; t < 4; t++)
                CPASYNC16(s2u(&sE[cur^1][(sr + t*8)*132 + sc]), &src[(sr + t*8)*128 + sc]);
            CPCOMMIT();
        }
        const int j0 = ch * CH;
        #pragma unroll
        for (int p = 0; p < 2; p++){
            const int jr = p*16 + jbase;
            const float* Er = &sE[cur][jr*132 + dbase];
            float4 ea = *(const float4*)(Er);
            float4 eb = *(const float4*)(Er + 4);
            #pragma unroll
            for (int i = 0; i < TI; i++){
                float A0 = fmaf(ea.x, Fq[i][0], qv[0]);
                float B0 = fmaf(ea.y, Fq[i][1], qv[1]);
                float A1 = fmaf(ea.z, Fq[i][2], qv[2]);
                float B1 = fmaf(ea.w, Fq[i][3], qv[3]);
                float A2 = fmaf(eb.x, Fq[i][4], qv[4]);
                float B2 = fmaf(eb.y, Fq[i][5], qv[5]);
                float A3 = fmaf(eb.z, Fq[i][6], qv[6]);
                float B3 = fmaf(eb.w, Fq[i][7], qv[7]);
                float s0 = (A0 + B0) * rcpa(A0 * B0);
                float s1 = (A1 + B1) * rcpa(A1 * B1);
                float s2 = (A2 + B2) * rcpa(A2 * B2);
                float s3 = (A3 + B3) * rcpa(A3 * B3);
                float s  = (s0 + s1) + (s2 + s3);
                // reduce across the 16 dq lanes (lane bits 1..4)
                s += __shfl_xor_sync(0xffffffffu, s, 2);
                s += __shfl_xor_sync(0xffffffffu, s, 4);
                s += __shfl_xor_sync(0xffffffffu, s, 8);
                s += __shfl_xor_sync(0xffffffffu, s, 16);
                if (lane < 2) ss[i*512 + j0 + jr] = cw - 2.f * s;
            }
        }
        if (ch < NCHUNK-1) CPWAIT0();
        __syncthreads();
    }

    // prefetch bmm chunk 0 (overlaps with softmax)
    const float* gI = &inp[b*LL*DD];
    #pragma unroll
    for (int t = 0; t < 4; t++)
        CPASYNC16(s2u(&sE[0][(sr + t*8)*132 + sc]), &gI[(sr + t*8)*128 + sc]);
    CPCOMMIT();

    // ---------------- softmax over j (one warp per i) ----------------
    if (warp < TI){
        float m = -1e30f;
        #pragma unroll
        for (int k = 0; k < 16; k++) m = fmaxf(m, ss[warp*512 + lane + k*32]);
        #pragma unroll
        for (int o = 16; o > 0; o >>= 1) m = fmaxf(m, __shfl_xor_sync(0xffffffffu, m, o));
        const float L2E = 1.4426950408889634f;
        float sum = 0.f;
        #pragma unroll
        for (int k = 0; k < 16; k++){
            float e = ex2a((ss[warp*512 + lane + k*32] - m) * L2E);
            ss[warp*512 + lane + k*32] = e;
            sum += e;
        }
        #pragma unroll
        for (int o = 16; o > 0; o >>= 1) sum += __shfl_xor_sync(0xffffffffu, sum, o);
        float inv = 1.0f / sum;   // accurate div, only 2048 total
        #pragma unroll
        for (int k = 0; k < 16; k++){
            float a = ss[warp*512 + lane + k*32] * inv;
            ss[warp*512 + lane + k*32] = a;
            attn[(b*LL + i0 + warp)*LL + lane + k*32] = a;
        }
    }
    CPWAIT0();
    __syncthreads();

    // ---------------- out = attn @ inp ----------------
    // Thread owns one d, all TI rows reuse each staged value; h splits j range.
    const int d = tid & 127, h = tid >> 7;
    float b0 = 0.f, b1 = 0.f, b2 = 0.f, b3 = 0.f;
    #pragma unroll 1
    for (int ch = 0; ch < NCHUNK; ch++){
        const int cur = ch & 1;
        if (ch < NCHUNK-1){
            const float* src = &gI[(ch+1)*CH*128];
            #pragma unroll
            for (int t = 0; t < 4; t++)
                CPASYNC16(s2u(&sE[cur^1][(sr + t*8)*132 + sc]), &src[(sr + t*8)*128 + sc]);
            CPCOMMIT();
        }
        const int j0 = ch * CH;
        const int jb = h * 16;
        #pragma unroll
        for (int jj = 0; jj < 16; jj++){
            float v = sE[cur][(jb + jj)*132 + d];
            b0 = fmaf(ss[0*512 + j0 + jb + jj], v, b0);
            b1 = fmaf(ss[1*512 + j0 + jb + jj], v, b1);
            b2 = fmaf(ss[2*512 + j0 + jb + jj], v, b2);
            b3 = fmaf(ss[3*512 + j0 + jb + jj], v, b3);
        }
        if (ch < NCHUNK-1) CPWAIT0();
        __syncthreads();
    }
    sp2[(h*TI + 0)*128 + d] = b0;
    sp2[(h*TI + 1)*128 + d] = b1;
    sp2[(h*TI + 2)*128 + d] = b2;
    sp2[(h*TI + 3)*128 + d] = b3;
    __syncthreads();
    #pragma unroll
    for (int idx = tid; idx < TI*128; idx += 256){
        int i = idx >> 7, dd = idx & 127;
        out[(b*LL + i0 + i)*128 + dd] = sp2[i*128 + dd] + sp2[(TI + i)*128 + dd];
    }
}

// ---------------------------------------------------------------------------
extern "C" void kernel_launch(void* const* d_in, const int* in_sizes, int n_in,
                              void* d_out, int out_size){
    const float* inp = (const float*)d_in[0];
    const float* Wu  = (const float*)d_in[1];
    const float* Ww  = (const float*)d_in[2];
    const float* Wv  = (const float*)d_in[3];
    float* out = (float*)d_out;

    float* attn;
    if (out_size >= BB*LL*DD + BB*LL*LL){
        attn = out + BB*LL*DD;               // tuple layout: [out | attn]
    } else {
        void* p = nullptr;
        cudaGetSymbolAddress(&p, g_attn_scratch);
        attn = (float*)p;
    }

    proj_kernel<<<dim3(BL/8, 2), 128>>>(inp, Wu, Ww);
    attn_kernel<<<BL/TI, 256>>>(inp, Wv, out, attn);
}

// round 11
// speedup vs baseline: 1.1391x; 1.0066x over previous
#include <cuda_runtime.h>
#include <cstdint>

#define BB 4
#define LL 512
#define DD 128
#define BL (BB*LL)
#define TI 4
#define CH 32          // j rows per staged chunk
#define NCHUNK (LL/CH) // 16

// Scratch (device globals; no allocation)
__device__ float g_E[BL*DD];                 // exp2(2*log2e * (inp @ Wu^T))  indexed by j
__device__ float g_F[BL*DD];                 // exp2(2*log2e * (inp @ Ww^T))  indexed by i
__device__ float g_attn_scratch[BB*LL*LL];   // used only if harness doesn't want attn

__device__ __forceinline__ float ex2a(float x){ float y; asm("ex2.approx.ftz.f32 %0, %1;" : "=f"(y) : "f"(x)); return y; }
__device__ __forceinline__ float rcpa(float x){ float y; asm("rcp.approx.ftz.f32 %0, %1;" : "=f"(y) : "f"(x)); return y; }
__device__ __forceinline__ uint32_t s2u(const void* p){ return (uint32_t)__cvta_generic_to_shared(p); }

// ---- packed f32x2 (sm_103a FFMA2 path; only reachable via PTX) ----
typedef unsigned long long u64;
__device__ __forceinline__ u64 pk2(float lo, float hi){ u64 r; asm("mov.b64 %0, {%1, %2};" : "=l"(r) : "f"(lo), "f"(hi)); return r; }
__device__ __forceinline__ void upk2(float& lo, float& hi, u64 x){ asm("mov.b64 {%0, %1}, %2;" : "=f"(lo), "=f"(hi) : "l"(x)); }
__device__ __forceinline__ u64 fma2(u64 a, u64 b, u64 c){ u64 d; asm("fma.rn.f32x2 %0, %1, %2, %3;" : "=l"(d) : "l"(a), "l"(b), "l"(c)); return d; }
__device__ __forceinline__ u64 add2(u64 a, u64 b){ u64 d; asm("add.rn.f32x2 %0, %1, %2;" : "=l"(d) : "l"(a), "l"(b)); return d; }
__device__ __forceinline__ u64 mul2(u64 a, u64 b){ u64 d; asm("mul.rn.f32x2 %0, %1, %2;" : "=l"(d) : "l"(a), "l"(b)); return d; }

#define CPASYNC16(dst, src) asm volatile("cp.async.cg.shared.global [%0], [%1], 16;" :: "r"(dst), "l"(src) : "memory")
#define CPCOMMIT()          asm volatile("cp.async.commit_group;" ::: "memory")
#define CPWAIT0()           asm volatile("cp.async.wait_group 0;" ::: "memory")

// ---------------------------------------------------------------------------
// Kernel A: qu = inp @ Wu^T, kw = inp @ Ww^T ; store E=exp2(K*qu), F=exp2(K*kw)
// ---------------------------------------------------------------------------
__global__ __launch_bounds__(128) void proj_kernel(const float* __restrict__ inp,
                                                   const float* __restrict__ Wu,
                                                   const float* __restrict__ Ww){
    __shared__ __align__(16) float sW[128*33];
    __shared__ __align__(16) float sI[8*33];
    const float* W  = blockIdx.y ? Ww  : Wu;
    float*       dst = blockIdx.y ? g_F : g_E;
    const int r0  = blockIdx.x * 8;
    const int tid = threadIdx.x;

    float acc[8];
    #pragma unroll
    for (int r = 0; r < 8; r++) acc[r] = 0.f;

    for (int dc = 0; dc < 128; dc += 32){
        for (int idx = tid; idx < 128*32; idx += 128){
            int t = idx >> 5, c = idx & 31;
            sW[t*33 + c] = W[t*128 + dc + c];
        }
        for (int idx = tid; idx < 8*32; idx += 128){
            int r = idx >> 5, c = idx & 31;
            sI[r*33 + c] = inp[(r0 + r)*128 + dc + c];
        }
        __syncthreads();
        #pragma unroll 8
        for (int c = 0; c < 32; c++){
            float w = sW[tid*33 + c];            // stride-33 -> conflict-free
            #pragma unroll
            for (int r = 0; r < 8; r++) acc[r] += sI[r*33 + c] * w;   // broadcast
        }
        __syncthreads();
    }
    const float K = 2.8853900817779268f;  // 2*log2(e)
    #pragma unroll
    for (int r = 0; r < 8; r++)
        dst[(r0 + r)*128 + tid] = ex2a(K * acc[r]);
}

// ---------------------------------------------------------------------------
// Kernel B: fused scores + softmax + attn write + out = attn @ inp
// grid 512, block 256, 4 blocks/SM.
// score[i][j] = cw - 2 * sum_d wv[d]*rcp(1+E[j,d]F[i,d])
// Pair trick (q=1/w): w0/A + w1/B = (A'+B')*rcp(A'*B') with A'=fmaf(e,Fq,q).
// All arithmetic except rcp in packed f32x2, pairs laid out as (d0,d2)/(d1,d3).
// Lane map: jg = lane&1 (j), dq = lane>>1 (8-wide d group).
// ---------------------------------------------------------------------------
__global__ __launch_bounds__(256, 4) void attn_kernel(const float* __restrict__ inp,
                                                      const float* __restrict__ wvp,
                                                      float* __restrict__ out,
                                                      float* __restrict__ attn){
    __shared__ __align__(16) float sE [2][CH*132];  // double-buffered E/inp chunk
    __shared__ __align__(16) float sF [TI*128];
    __shared__ __align__(16) float swv[128];
    __shared__ __align__(16) float ss [TI*512];     // scores -> attn row cache
    __shared__ __align__(16) float sp2[2*TI*128];   // bmm partials per j-half
    const int tid  = threadIdx.x;
    const int b    = blockIdx.x >> 7;               // /128
    const int i0   = (blockIdx.x & 127) * TI;
    const int lane = tid & 31;
    const int warp = tid >> 5;

    if (tid < 128) swv[tid] = wvp[tid];
    for (int idx = tid; idx < TI*128; idx += 256)
        sF[idx] = g_F[(b*LL + i0 + (idx >> 7))*128 + (idx & 127)];
    __syncthreads();

    // cw = sum(wv) via shuffle reduction
    float cw = swv[lane] + swv[lane+32] + swv[lane+64] + swv[lane+96];
    #pragma unroll
    for (int o = 16; o > 0; o >>= 1) cw += __shfl_xor_sync(0xffffffffu, cw, o);

    const int jg    = lane & 1;        // j within warp pair
    const int dq    = lane >> 1;       // d-group (0..15), 8 d each
    const int dbase = dq * 8;
    const int jbase = warp * 2 + jg;   // j within 16-row pass

    // q = 1/wv; packed state: pairs are (d0,d1),(d2,d3),(d4,d5),(d6,d7);
    // A-slots = even elems packed (d0,d2)/(d4,d6), B-slots = odd (d1,d3)/(d5,d7).
    float qs[8];
    #pragma unroll
    for (int k = 0; k < 8; k++) qs[k] = 1.0f / swv[dbase + k];
    const u64 qA0 = pk2(qs[0], qs[2]), qB0 = pk2(qs[1], qs[3]);
    const u64 qA1 = pk2(qs[4], qs[6]), qB1 = pk2(qs[5], qs[7]);
    u64 FqA0[TI], FqB0[TI], FqA1[TI], FqB1[TI];
    #pragma unroll
    for (int i = 0; i < TI; i++){
        const float* Fr = &sF[i*128 + dbase];
        FqA0[i] = pk2(Fr[0]*qs[0], Fr[2]*qs[2]);
        FqB0[i] = pk2(Fr[1]*qs[1], Fr[3]*qs[3]);
        FqA1[i] = pk2(Fr[4]*qs[4], Fr[6]*qs[6]);
        FqB1[i] = pk2(Fr[5]*qs[5], Fr[7]*qs[7]);
    }

    const float* gE = &g_E[b*LL*DD];
    const int sr = tid >> 5, sc = (tid & 31) * 4;   // staging row/col

    // stage chunk 0 into buffer 0
    #pragma unroll
    for (int t = 0; t < 4; t++)
        CPASYNC16(s2u(&sE[0][(sr + t*8)*132 + sc]), &gE[(sr + t*8)*128 + sc]);
    CPCOMMIT(); CPWAIT0();
    __syncthreads();

    // ---------------- scores ----------------
    #pragma unroll 1
    for (int ch = 0; ch < NCHUNK; ch++){
        const int cur = ch & 1;
        if (ch < NCHUNK-1){
            const float* src = &gE[(ch+1)*CH*128];
            #pragma unroll
            for (int t = 0; t < 4; t++)
                CPASYNC16(s2u(&sE[cur^1][(sr + t*8)*132 + sc]), &src[(sr + t*8)*128 + sc]);
            CPCOMMIT();
        }
        const int j0 = ch * CH;
        #pragma unroll
        for (int p = 0; p < 2; p++){
            const int jr = p*16 + jbase;
            const float* Er = &sE[cur][jr*132 + dbase];
            float4 ea = *(const float4*)(Er);
            float4 eb = *(const float4*)(Er + 4);
            const u64 e02 = pk2(ea.x, ea.z), e13 = pk2(ea.y, ea.w);
            const u64 e46 = pk2(eb.x, eb.z), e57 = pk2(eb.y, eb.w);
            #pragma unroll
            for (int i = 0; i < TI; i++){
                u64 PA0 = fma2(e02, FqA0[i], qA0);
                u64 PB0 = fma2(e13, FqB0[i], qB0);
                u64 PA1 = fma2(e46, FqA1[i], qA1);
                u64 PB1 = fma2(e57, FqB1[i], qB1);
                u64 S0 = add2(PA0, PB0);
                u64 Q0 = mul2(PA0, PB0);
                u64 S1 = add2(PA1, PB1);
                u64 Q1 = mul2(PA1, PB1);
                float qa, qb, qc, qd;
                upk2(qa, qb, Q0); upk2(qc, qd, Q1);
                u64 R0 = pk2(rcpa(qa), rcpa(qb));
                u64 R1 = pk2(rcpa(qc), rcpa(qd));
                u64 T  = fma2(S1, R1, mul2(S0, R0));
                float tlo, thi; upk2(tlo, thi, T);
                float s = tlo + thi;
                // reduce across the 16 dq lanes (lane bits 1..4)
                s += __shfl_xor_sync(0xffffffffu, s, 2);
                s += __shfl_xor_sync(0xffffffffu, s, 4);
                s += __shfl_xor_sync(0xffffffffu, s, 8);
                s += __shfl_xor_sync(0xffffffffu, s, 16);
                if (lane < 2) ss[i*512 + j0 + jr] = cw - 2.f * s;
            }
        }
        if (ch < NCHUNK-1) CPWAIT0();
        __syncthreads();
    }

    // prefetch bmm chunk 0 (overlaps with softmax)
    const float* gI = &inp[b*LL*DD];
    #pragma unroll
    for (int t = 0; t < 4; t++)
        CPASYNC16(s2u(&sE[0][(sr + t*8)*132 + sc]), &gI[(sr + t*8)*128 + sc]);
    CPCOMMIT();

    // ---------------- softmax over j (one warp per i) ----------------
    if (warp < TI){
        float m = -1e30f;
        #pragma unroll
        for (int k = 0; k < 16; k++) m = fmaxf(m, ss[warp*512 + lane + k*32]);
        #pragma unroll
        for (int o = 16; o > 0; o >>= 1) m = fmaxf(m, __shfl_xor_sync(0xffffffffu, m, o));
        const float L2E = 1.4426950408889634f;
        float sum = 0.f;
        #pragma unroll
        for (int k = 0; k < 16; k++){
            float e = ex2a((ss[warp*512 + lane + k*32] - m) * L2E);
            ss[warp*512 + lane + k*32] = e;
            sum += e;
        }
        #pragma unroll
        for (int o = 16; o > 0; o >>= 1) sum += __shfl_xor_sync(0xffffffffu, sum, o);
        float inv = 1.0f / sum;   // accurate div, only 2048 total
        #pragma unroll
        for (int k = 0; k < 16; k++){
            float a = ss[warp*512 + lane + k*32] * inv;
            ss[warp*512 + lane + k*32] = a;
            attn[(b*LL + i0 + warp)*LL + lane + k*32] = a;
        }
    }
    CPWAIT0();
    __syncthreads();

    // ---------------- out = attn @ inp ----------------
    const int d = tid & 127, h = tid >> 7;
    float b0 = 0.f, b1 = 0.f, b2 = 0.f, b3 = 0.f;
    #pragma unroll 1
    for (int ch = 0; ch < NCHUNK; ch++){
        const int cur = ch & 1;
        if (ch < NCHUNK-1){
            const float* src = &gI[(ch+1)*CH*128];
            #pragma unroll
            for (int t = 0; t < 4; t++)
                CPASYNC16(s2u(&sE[cur^1][(sr + t*8)*132 + sc]), &src[(sr + t*8)*128 + sc]);
            CPCOMMIT();
        }
        const int j0 = ch * CH;
        const int jb = h * 16;
        #pragma unroll
        for (int jj = 0; jj < 16; jj++){
            float v = sE[cur][(jb + jj)*132 + d];
            b0 = fmaf(ss[0*512 + j0 + jb + jj], v, b0);
            b1 = fmaf(ss[1*512 + j0 + jb + jj], v, b1);
            b2 = fmaf(ss[2*512 + j0 + jb + jj], v, b2);
            b3 = fmaf(ss[3*512 + j0 + jb + jj], v, b3);
        }
        if (ch < NCHUNK-1) CPWAIT0();
        __syncthreads();
    }
    sp2[(h*TI + 0)*128 + d] = b0;
    sp2[(h*TI + 1)*128 + d] = b1;
    sp2[(h*TI + 2)*128 + d] = b2;
    sp2[(h*TI + 3)*128 + d] = b3;
    __syncthreads();
    #pragma unroll
    for (int idx = tid; idx < TI*128; idx += 256){
        int i = idx >> 7, dd = idx & 127;
        out[(b*LL + i0 + i)*128 + dd] = sp2[i*128 + dd] + sp2[(TI + i)*128 + dd];
    }
}

// ---------------------------------------------------------------------------
extern "C" void kernel_launch(void* const* d_in, const int* in_sizes, int n_in,
                              void* d_out, int out_size){
    const float* inp = (const float*)d_in[0];
    const float* Wu  = (const float*)d_in[1];
    const float* Ww  = (const float*)d_in[2];
    const float* Wv  = (const float*)d_in[3];
    float* out = (float*)d_out;

    float* attn;
    if (out_size >= BB*LL*DD + BB*LL*LL){
        attn = out + BB*LL*DD;               // tuple layout: [out | attn]
    } else {
        void* p = nullptr;
        cudaGetSymbolAddress(&p, g_attn_scratch);
        attn = (float*)p;
    }

    proj_kernel<<<dim3(BL/8, 2), 128>>>(inp, Wu, Ww);
    attn_kernel<<<BL/TI, 256>>>(inp, Wv, out, attn);
}

// round 12
// speedup vs baseline: 1.3528x; 1.1876x over previous
#include <cuda_runtime.h>
#include <cstdint>

#define BB 4
#define LL 512
#define DD 128
#define BL (BB*LL)
#define TI 4
#define JB 256          // j per score block (half of L)
#define CH 16           // j rows per staged chunk
#define NCH (JB/CH)     // 16

// Scratch (device globals; no allocation)
__device__ float  g_E[BL*DD];               // exp2(2*log2e * (inp @ Wu^T))  indexed by j
__device__ float  g_F[BL*DD];               // exp2(2*log2e * (inp @ Ww^T))  indexed by i
__device__ float2 g_stats[BL*2];            // per (row, j-half): (m_loc, sum_loc)
__device__ float  g_outpart[BL*2*DD];       // per (row, j-half) partial bmm
__device__ float  g_attn_scratch[BB*LL*LL]; // used only if harness doesn't want attn

__device__ __forceinline__ float ex2a(float x){ float y; asm("ex2.approx.ftz.f32 %0, %1;" : "=f"(y) : "f"(x)); return y; }
__device__ __forceinline__ float rcpa(float x){ float y; asm("rcp.approx.ftz.f32 %0, %1;" : "=f"(y) : "f"(x)); return y; }
__device__ __forceinline__ uint32_t s2u(const void* p){ return (uint32_t)__cvta_generic_to_shared(p); }

#define CPASYNC16(dst, src) asm volatile("cp.async.cg.shared.global [%0], [%1], 16;" :: "r"(dst), "l"(src) : "memory")
#define CPCOMMIT()          asm volatile("cp.async.commit_group;" ::: "memory")
#define CPWAIT0()           asm volatile("cp.async.wait_group 0;" ::: "memory")

// ---------------------------------------------------------------------------
// Kernel A: qu = inp @ Wu^T, kw = inp @ Ww^T ; store E=exp2(K*qu), F=exp2(K*kw)
// ---------------------------------------------------------------------------
__global__ __launch_bounds__(128) void proj_kernel(const float* __restrict__ inp,
                                                   const float* __restrict__ Wu,
                                                   const float* __restrict__ Ww){
    __shared__ __align__(16) float sW[128*33];
    __shared__ __align__(16) float sI[8*33];
    const float* W  = blockIdx.y ? Ww  : Wu;
    float*       dst = blockIdx.y ? g_F : g_E;
    const int r0  = blockIdx.x * 8;
    const int tid = threadIdx.x;

    float acc[8];
    #pragma unroll
    for (int r = 0; r < 8; r++) acc[r] = 0.f;

    for (int dc = 0; dc < 128; dc += 32){
        for (int idx = tid; idx < 128*32; idx += 128){
            int t = idx >> 5, c = idx & 31;
            sW[t*33 + c] = W[t*128 + dc + c];
        }
        for (int idx = tid; idx < 8*32; idx += 128){
            int r = idx >> 5, c = idx & 31;
            sI[r*33 + c] = inp[(r0 + r)*128 + dc + c];
        }
        __syncthreads();
        #pragma unroll 8
        for (int c = 0; c < 32; c++){
            float w = sW[tid*33 + c];            // stride-33 -> conflict-free
            #pragma unroll
            for (int r = 0; r < 8; r++) acc[r] += sI[r*33 + c] * w;   // broadcast
        }
        __syncthreads();
    }
    const float K = 2.8853900817779268f;  // 2*log2(e)
    #pragma unroll
    for (int r = 0; r < 8; r++)
        dst[(r0 + r)*128 + tid] = ex2a(K * acc[r]);
}

// ---------------------------------------------------------------------------
// Kernel B (phase A): scores + LOCAL softmax + attn p-write + PARTIAL bmm
// for one (b, i-quad, j-half). grid 1024, block 128, 8 blocks/SM.
// score[i][j] = cw - 2*sum_d wv_d * rcp(1+E[j,d]F[i,d])  (pair trick, q=1/w)
// Lane map: jg = lane&1 (j), dq = lane>>1 (8-wide d group). Fq in regs.
// ---------------------------------------------------------------------------
__global__ __launch_bounds__(128, 8) void attnA_kernel(const float* __restrict__ inp,
                                                       const float* __restrict__ wvp,
                                                       float* __restrict__ attn){
    __shared__ __align__(16) float sE [2][CH*132];  // double-buffered E/inp chunk (16.5KB)
    __shared__ __align__(16) float sF [TI*128];
    __shared__ __align__(16) float swv[128];
    __shared__ __align__(16) float ss [TI*JB];      // scores -> p cache (4KB)
    const int tid  = threadIdx.x;
    const int lane = tid & 31;
    const int warp = tid >> 5;
    const int bid  = blockIdx.x;
    const int jh   = bid & 1;                 // j-half
    const int iq   = (bid >> 1) & 127;        // i-quad within batch
    const int b    = bid >> 8;
    const int i0   = iq * TI;
    const int j0g  = jh * JB;

    swv[tid] = wvp[tid];
    #pragma unroll
    for (int k = 0; k < TI; k++)
        sF[k*128 + tid] = g_F[(b*LL + i0 + k)*128 + tid];
    __syncthreads();

    // cw = sum(wv)
    float cw = swv[lane] + swv[lane+32] + swv[lane+64] + swv[lane+96];
    #pragma unroll
    for (int o = 16; o > 0; o >>= 1) cw += __shfl_xor_sync(0xffffffffu, cw, o);

    const int dbase = (lane >> 1) * 8;
    float qv[8];
    #pragma unroll
    for (int k = 0; k < 8; k++) qv[k] = 1.0f / swv[dbase + k];
    float Fq[TI][8];
    #pragma unroll
    for (int i = 0; i < TI; i++)
        #pragma unroll
        for (int k = 0; k < 8; k++) Fq[i][k] = sF[i*128 + dbase + k] * qv[k];

    const float* gE = &g_E[(b*LL + j0g)*DD];
    const float* gI = &inp [(b*LL + j0g)*DD];
    const int sr = tid >> 5, sc = (tid & 31) * 4;   // staging: rows sr+4t, 4 float4/thread

    // stage chunk 0
    #pragma unroll
    for (int t = 0; t < 4; t++)
        CPASYNC16(s2u(&sE[0][(sr + t*4)*132 + sc]), &gE[(sr + t*4)*128 + sc]);
    CPCOMMIT(); CPWAIT0();
    __syncthreads();

    // ---------------- scores ----------------
    #pragma unroll 1
    for (int ch = 0; ch < NCH; ch++){
        const int cur = ch & 1;
        if (ch < NCH-1){
            const float* src = &gE[(ch+1)*CH*128];
            #pragma unroll
            for (int t = 0; t < 4; t++)
                CPASYNC16(s2u(&sE[cur^1][(sr + t*4)*132 + sc]), &src[(sr + t*4)*128 + sc]);
            CPCOMMIT();
        }
        #pragma unroll
        for (int p = 0; p < 2; p++){
            const int jr = p*8 + warp*2 + (lane & 1);
            const float* Er = &sE[cur][jr*132 + dbase];
            float4 ea = *(const float4*)(Er);
            float4 eb = *(const float4*)(Er + 4);
            float s[TI];
            #pragma unroll
            for (int i = 0; i < TI; i++){
                float A0 = fmaf(ea.x, Fq[i][0], qv[0]);
                float B0 = fmaf(ea.y, Fq[i][1], qv[1]);
                float A1 = fmaf(ea.z, Fq[i][2], qv[2]);
                float B1 = fmaf(ea.w, Fq[i][3], qv[3]);
                float A2 = fmaf(eb.x, Fq[i][4], qv[4]);
                float B2 = fmaf(eb.y, Fq[i][5], qv[5]);
                float A3 = fmaf(eb.z, Fq[i][6], qv[6]);
                float B3 = fmaf(eb.w, Fq[i][7], qv[7]);
                float s0 = (A0 + B0) * rcpa(A0 * B0);
                float s1 = (A1 + B1) * rcpa(A1 * B1);
                float s2 = (A2 + B2) * rcpa(A2 * B2);
                float s3 = (A3 + B3) * rcpa(A3 * B3);
                s[i] = (s0 + s1) + (s2 + s3);
            }
            // halving-tree reduction over the 16 dq lanes (bits 1..4), 5 shfl
            float g0 = (lane & 2) ? s[0] : s[2];
            float r0 = __shfl_xor_sync(0xffffffffu, g0, 2);
            float n0 = ((lane & 2) ? s[2] : s[0]) + r0;      // i0 (bit1=0) / i2 (bit1=1)
            float g1 = (lane & 2) ? s[1] : s[3];
            float r1 = __shfl_xor_sync(0xffffffffu, g1, 2);
            float n1 = ((lane & 2) ? s[3] : s[1]) + r1;      // i1 / i3
            float g2 = (lane & 4) ? n0 : n1;
            float r2 = __shfl_xor_sync(0xffffffffu, g2, 4);
            float m  = ((lane & 4) ? n1 : n0) + r2;          // i = 2*bit1 + bit2
            m += __shfl_xor_sync(0xffffffffu, m, 8);
            m += __shfl_xor_sync(0xffffffffu, m, 16);
            if (lane < 8){
                int ii   = 2*((lane >> 1) & 1) + ((lane >> 2) & 1);
                int jloc = ch*CH + jr;
                ss[ii*JB + jloc] = cw - 2.f * m;
            }
        }
        if (ch < NCH-1) CPWAIT0();
        __syncthreads();
    }

    // prefetch bmm chunk 0 (overlaps softmax)
    #pragma unroll
    for (int t = 0; t < 4; t++)
        CPASYNC16(s2u(&sE[0][(sr + t*4)*132 + sc]), &gI[(sr + t*4)*128 + sc]);
    CPCOMMIT();

    // ---------------- local softmax over this j-half (warp w = row w) ----------------
    {
        float mx = -1e30f;
        #pragma unroll
        for (int k = 0; k < 8; k++) mx = fmaxf(mx, ss[warp*JB + lane + k*32]);
        #pragma unroll
        for (int o = 16; o > 0; o >>= 1) mx = fmaxf(mx, __shfl_xor_sync(0xffffffffu, mx, o));
        const float L2E = 1.4426950408889634f;
        float sum = 0.f;
        #pragma unroll
        for (int k = 0; k < 8; k++){
            float e = ex2a((ss[warp*JB + lane + k*32] - mx) * L2E);
            ss[warp*JB + lane + k*32] = e;
            attn[(b*LL + i0 + warp)*LL + j0g + lane + k*32] = e;   // unnormalized p
            sum += e;
        }
        #pragma unroll
        for (int o = 16; o > 0; o >>= 1) sum += __shfl_xor_sync(0xffffffffu, sum, o);
        if (lane == 0)
            g_stats[(b*LL + i0 + warp)*2 + jh] = make_float2(mx, sum);
    }
    CPWAIT0();
    __syncthreads();

    // ---------------- partial bmm: outpart[i][d] = sum_{j in half} p_ij * inp[j][d] ----------------
    const int d = tid;   // 0..127
    float a0 = 0.f, a1 = 0.f, a2 = 0.f, a3 = 0.f;
    #pragma unroll 1
    for (int ch = 0; ch < NCH; ch++){
        const int cur = ch & 1;
        if (ch < NCH-1){
            const float* src = &gI[(ch+1)*CH*128];
            #pragma unroll
            for (int t = 0; t < 4; t++)
                CPASYNC16(s2u(&sE[cur^1][(sr + t*4)*132 + sc]), &src[(sr + t*4)*128 + sc]);
            CPCOMMIT();
        }
        const int jc = ch * CH;
        #pragma unroll
        for (int jq = 0; jq < 4; jq++){
            float4 p0 = *(const float4*)&ss[0*JB + jc + jq*4];
            float4 p1 = *(const float4*)&ss[1*JB + jc + jq*4];
            float4 p2 = *(const float4*)&ss[2*JB + jc + jq*4];
            float4 p3 = *(const float4*)&ss[3*JB + jc + jq*4];
            const float* vb = &sE[cur][(jq*4)*132 + d];
            float v0 = vb[0*132], v1 = vb[1*132], v2 = vb[2*132], v3 = vb[3*132];
            a0 = fmaf(p0.x, v0, a0); a1 = fmaf(p1.x, v0, a1); a2 = fmaf(p2.x, v0, a2); a3 = fmaf(p3.x, v0, a3);
            a0 = fmaf(p0.y, v1, a0); a1 = fmaf(p1.y, v1, a1); a2 = fmaf(p2.y, v1, a2); a3 = fmaf(p3.y, v1, a3);
            a0 = fmaf(p0.z, v2, a0); a1 = fmaf(p1.z, v2, a1); a2 = fmaf(p2.z, v2, a2); a3 = fmaf(p3.z, v2, a3);
            a0 = fmaf(p0.w, v3, a0); a1 = fmaf(p1.w, v3, a1); a2 = fmaf(p2.w, v3, a2); a3 = fmaf(p3.w, v3, a3);
        }
        if (ch < NCH-1) CPWAIT0();
        __syncthreads();
    }
    g_outpart[((b*LL + i0 + 0)*2 + jh)*128 + d] = a0;
    g_outpart[((b*LL + i0 + 1)*2 + jh)*128 + d] = a1;
    g_outpart[((b*LL + i0 + 2)*2 + jh)*128 + d] = a2;
    g_outpart[((b*LL + i0 + 3)*2 + jh)*128 + d] = a3;
}

// ---------------------------------------------------------------------------
// Kernel C (merge): combine the two j-halves per row. grid BL=2048, block 128.
// out = (op0*c0 + op1*c1)/S ; attn[j in half h] *= c_h/S ; c_h = e^{m_h - M}.
// ---------------------------------------------------------------------------
__global__ __launch_bounds__(128) void merge_kernel(float* __restrict__ out,
                                                    float* __restrict__ attn){
    const int row = blockIdx.x;
    const int d   = threadIdx.x;
    float2 st0 = g_stats[row*2 + 0];
    float2 st1 = g_stats[row*2 + 1];
    const float L2E = 1.4426950408889634f;
    float M  = fmaxf(st0.x, st1.x);
    float c0 = ex2a((st0.x - M) * L2E);
    float c1 = ex2a((st1.x - M) * L2E);
    float S  = st0.y*c0 + st1.y*c1;
    float inv = 1.0f / S;
    out[row*128 + d] = (g_outpart[(row*2 + 0)*128 + d]*c0
                      + g_outpart[(row*2 + 1)*128 + d]*c1) * inv;
    float f0 = c0*inv, f1 = c1*inv;
    #pragma unroll
    for (int k = 0; k < 4; k++){
        int j = d + k*128;
        attn[row*512 + j] *= (k < 2) ? f0 : f1;
    }
}

// ---------------------------------------------------------------------------
extern "C" void kernel_launch(void* const* d_in, const int* in_sizes, int n_in,
                              void* d_out, int out_size){
    const float* inp = (const float*)d_in[0];
    const float* Wu  = (const float*)d_in[1];
    const float* Ww  = (const float*)d_in[2];
    const float* Wv  = (const float*)d_in[3];
    float* out = (float*)d_out;

    float* attn;
    if (out_size >= BB*LL*DD + BB*LL*LL){
        attn = out + BB*LL*DD;               // tuple layout: [out | attn]
    } else {
        void* p = nullptr;
        cudaGetSymbolAddress(&p, g_attn_scratch);
        attn = (float*)p;
    }

    proj_kernel <<<dim3(BL/8, 2), 128>>>(inp, Wu, Ww);
    attnA_kernel<<<BL/TI*2, 128>>>(inp, Wv, attn);
    merge_kernel<<<BL, 128>>>(out, attn);
}

// round 14
// speedup vs baseline: 1.5295x; 1.1306x over previous
#include <cuda_runtime.h>
#include <cstdint>

#define BB 4
#define LL 512
#define DD 128
#define BL (BB*LL)
#define TI 4
#define JB 256          // j per score block (half of L)
#define CH 16           // j rows per staged chunk
#define NCH (JB/CH)     // 16
#define PR 16           // rows per proj block
#define QW 36           // padded W-quarter row stride (32 c + 4 pad)

// Scratch (device globals; no allocation)
__device__ float  g_E[BL*DD];               // exp2(2*log2e * (inp @ Wu^T))  indexed by j
__device__ float  g_F[BL*DD];               // exp2(2*log2e * (inp @ Ww^T))  indexed by i
__device__ float2 g_stats[BL*2];            // per (row, j-half): (m_loc, sum_loc)
__device__ float  g_outpart[BL*2*DD];       // per (row, j-half) partial bmm
__device__ float  g_attn_scratch[BB*LL*LL]; // used only if harness doesn't want attn

__device__ __forceinline__ float ex2a(float x){ float y; asm("ex2.approx.ftz.f32 %0, %1;" : "=f"(y) : "f"(x)); return y; }
__device__ __forceinline__ float rcpa(float x){ float y; asm("rcp.approx.ftz.f32 %0, %1;" : "=f"(y) : "f"(x)); return y; }
__device__ __forceinline__ uint32_t s2u(const void* p){ return (uint32_t)__cvta_generic_to_shared(p); }

#define CPASYNC16(dst, src) asm volatile("cp.async.cg.shared.global [%0], [%1], 16;" :: "r"(dst), "l"(src) : "memory")
#define CPCOMMIT()          asm volatile("cp.async.commit_group;" ::: "memory")
#define CPWAIT0()           asm volatile("cp.async.wait_group 0;" ::: "memory")

// ---------------------------------------------------------------------------
// Kernel A v2: qu = inp @ Wu^T, kw = inp @ Ww^T ; store E=exp2(K*qu), F=exp2(K*kw)
// 16 rows x 256 threads (d = tid&127, h = tid>>7 owns a 16-c half of each
// 32-c W quarter). W quarters double-buffered via cp.async. grid (128, 2).
// ---------------------------------------------------------------------------
__global__ __launch_bounds__(256) void proj_kernel(const float* __restrict__ inp,
                                                   const float* __restrict__ Wu,
                                                   const float* __restrict__ Ww){
    __shared__ __align__(16) float sW[2][128*QW];   // 2 x 18.4KB
    __shared__ __align__(16) float sI[PR*132];      // 8.4KB
    const float* W  = blockIdx.y ? Ww : Wu;
    float*      dst = blockIdx.y ? g_F : g_E;
    const int r0  = blockIdx.x * PR;
    const int tid = threadIdx.x;
    const int d = tid & 127, h = tid >> 7;

    // stage sI (all 128 c, 16 rows) + W quarter 0
    #pragma unroll
    for (int k = 0; k < 2; k++){
        int idx = tid + k*256;                 // 0..511 : 16 rows x 32 float4
        int r = idx >> 5, c4 = idx & 31;
        CPASYNC16(s2u(&sI[r*132 + c4*4]), &inp[(r0 + r)*128 + c4*4]);
    }
    #pragma unroll
    for (int k = 0; k < 4; k++){
        int idx = tid + k*256;                 // 0..1023 : 128 rows x 8 float4
        int t = idx >> 3, c4 = idx & 7;
        CPASYNC16(s2u(&sW[0][t*QW + c4*4]), &W[t*128 + c4*4]);
    }
    CPCOMMIT(); CPWAIT0();
    __syncthreads();

    float acc[PR];
    #pragma unroll
    for (int r = 0; r < PR; r++) acc[r] = 0.f;

    #pragma unroll
    for (int q = 0; q < 4; q++){
        const int cur = q & 1;
        if (q < 3){
            #pragma unroll
            for (int k = 0; k < 4; k++){
                int idx = tid + k*256;
                int t = idx >> 3, c4 = idx & 7;
                CPASYNC16(s2u(&sW[cur^1][t*QW + c4*4]), &W[t*128 + (q+1)*32 + c4*4]);
            }
            CPCOMMIT();
        }
        const float* wrow = &sW[cur][d*QW + h*16];
        const float* irow = &sI[q*32 + h*16];
        #pragma unroll
        for (int c4 = 0; c4 < 4; c4++){
            float4 w4 = *(const float4*)(wrow + c4*4);
            #pragma unroll
            for (int r = 0; r < PR; r++){
                float4 i4 = *(const float4*)(irow + r*132 + c4*4);   // broadcast
                acc[r] = fmaf(i4.x, w4.x, acc[r]);
                acc[r] = fmaf(i4.y, w4.y, acc[r]);
                acc[r] = fmaf(i4.z, w4.z, acc[r]);
                acc[r] = fmaf(i4.w, w4.w, acc[r]);
            }
        }
        if (q < 3) CPWAIT0();
        __syncthreads();
    }

    // h-reduction via smem overlay on sW[0] (last compute phase read sW[1])
    float* sP = &sW[0][0];                      // 2*PR*128 = 4096 floats
    #pragma unroll
    for (int r = 0; r < PR; r++) sP[h*PR*128 + r*128 + d] = acc[r];
    __syncthreads();
    const float K = 2.8853900817779268f;        // 2*log2(e)
    #pragma unroll
    for (int k = 0; k < 8; k++){
        int idx = tid + k*256;                  // 0..2047
        int r = idx >> 7, dd = idx & 127;
        float v = sP[r*128 + dd] + sP[PR*128 + r*128 + dd];
        dst[(r0 + r)*128 + dd] = ex2a(K * v);
    }
}

// ---------------------------------------------------------------------------
// Kernel B (phase A): scores + LOCAL softmax + attn p-write + PARTIAL bmm
// for one (b, i-quad, j-half). grid 1024, block 128, 8 blocks/SM.
// score[i][j] = cw - 2*sum_d wv_d * rcp(1+E[j,d]F[i,d])  (pair trick, q=1/w)
// Lane map: jg = lane&1 (j), dq = lane>>1 (8-wide d group). Fq in regs.
// ---------------------------------------------------------------------------
__global__ __launch_bounds__(128, 8) void attnA_kernel(const float* __restrict__ inp,
                                                       const float* __restrict__ wvp,
                                                       float* __restrict__ attn){
    __shared__ __align__(16) float sE [2][CH*132];  // double-buffered E/inp chunk (16.5KB)
    __shared__ __align__(16) float sF [TI*128];
    __shared__ __align__(16) float swv[128];
    __shared__ __align__(16) float ss [TI*JB];      // scores -> p cache (4KB)
    const int tid  = threadIdx.x;
    const int lane = tid & 31;
    const int warp = tid >> 5;
    const int bid  = blockIdx.x;
    const int jh   = bid & 1;                 // j-half
    const int iq   = (bid >> 1) & 127;        // i-quad within batch
    const int b    = bid >> 8;
    const int i0   = iq * TI;
    const int j0g  = jh * JB;

    swv[tid] = wvp[tid];
    #pragma unroll
    for (int k = 0; k < TI; k++)
        sF[k*128 + tid] = g_F[(b*LL + i0 + k)*128 + tid];
    __syncthreads();

    // cw = sum(wv)
    float cw = swv[lane] + swv[lane+32] + swv[lane+64] + swv[lane+96];
    #pragma unroll
    for (int o = 16; o > 0; o >>= 1) cw += __shfl_xor_sync(0xffffffffu, cw, o);

    const int dbase = (lane >> 1) * 8;
    float qv[8];
    #pragma unroll
    for (int k = 0; k < 8; k++) qv[k] = 1.0f / swv[dbase + k];
    float Fq[TI][8];
    #pragma unroll
    for (int i = 0; i < TI; i++)
        #pragma unroll
        for (int k = 0; k < 8; k++) Fq[i][k] = sF[i*128 + dbase + k] * qv[k];

    const float* gE = &g_E[(b*LL + j0g)*DD];
    const float* gI = &inp [(b*LL + j0g)*DD];
    const int sr = tid >> 5, sc = (tid & 31) * 4;   // staging: rows sr+4t, 4 float4/thread

    // stage chunk 0
    #pragma unroll
    for (int t = 0; t < 4; t++)
        CPASYNC16(s2u(&sE[0][(sr + t*4)*132 + sc]), &gE[(sr + t*4)*128 + sc]);
    CPCOMMIT(); CPWAIT0();
    __syncthreads();

    // ---------------- scores ----------------
    #pragma unroll 1
    for (int ch = 0; ch < NCH; ch++){
        const int cur = ch & 1;
        if (ch < NCH-1){
            const float* src = &gE[(ch+1)*CH*128];
            #pragma unroll
            for (int t = 0; t < 4; t++)
                CPASYNC16(s2u(&sE[cur^1][(sr + t*4)*132 + sc]), &src[(sr + t*4)*128 + sc]);
            CPCOMMIT();
        }
        #pragma unroll
        for (int p = 0; p < 2; p++){
            const int jr = p*8 + warp*2 + (lane & 1);
            const float* Er = &sE[cur][jr*132 + dbase];
            float4 ea = *(const float4*)(Er);
            float4 eb = *(const float4*)(Er + 4);
            float s[TI];
            #pragma unroll
            for (int i = 0; i < TI; i++){
                float A0 = fmaf(ea.x, Fq[i][0], qv[0]);
                float B0 = fmaf(ea.y, Fq[i][1], qv[1]);
                float A1 = fmaf(ea.z, Fq[i][2], qv[2]);
                float B1 = fmaf(ea.w, Fq[i][3], qv[3]);
                float A2 = fmaf(eb.x, Fq[i][4], qv[4]);
                float B2 = fmaf(eb.y, Fq[i][5], qv[5]);
                float A3 = fmaf(eb.z, Fq[i][6], qv[6]);
                float B3 = fmaf(eb.w, Fq[i][7], qv[7]);
                float s0 = (A0 + B0) * rcpa(A0 * B0);
                float s1 = (A1 + B1) * rcpa(A1 * B1);
                float s2 = (A2 + B2) * rcpa(A2 * B2);
                float s3 = (A3 + B3) * rcpa(A3 * B3);
                s[i] = (s0 + s1) + (s2 + s3);
            }
            // halving-tree reduction over the 16 dq lanes (bits 1..4), 5 shfl
            float g0 = (lane & 2) ? s[0] : s[2];
            float r0 = __shfl_xor_sync(0xffffffffu, g0, 2);
            float n0 = ((lane & 2) ? s[2] : s[0]) + r0;      // i0 (bit1=0) / i2 (bit1=1)
            float g1 = (lane & 2) ? s[1] : s[3];
            float r1 = __shfl_xor_sync(0xffffffffu, g1, 2);
            float n1 = ((lane & 2) ? s[3] : s[1]) + r1;      // i1 / i3
            float g2 = (lane & 4) ? n0 : n1;
            float r2 = __shfl_xor_sync(0xffffffffu, g2, 4);
            float m  = ((lane & 4) ? n1 : n0) + r2;          // i = 2*bit1 + bit2
            m += __shfl_xor_sync(0xffffffffu, m, 8);
            m += __shfl_xor_sync(0xffffffffu, m, 16);
            if (lane < 8){
                int ii   = 2*((lane >> 1) & 1) + ((lane >> 2) & 1);
                int jloc = ch*CH + jr;
                ss[ii*JB + jloc] = cw - 2.f * m;
            }
        }
        if (ch < NCH-1) CPWAIT0();
        __syncthreads();
    }

    // prefetch bmm chunk 0 (overlaps softmax)
    #pragma unroll
    for (int t = 0; t < 4; t++)
        CPASYNC16(s2u(&sE[0][(sr + t*4)*132 + sc]), &gI[(sr + t*4)*128 + sc]);
    CPCOMMIT();

    // ---------------- local softmax over this j-half (warp w = row w) ----------------
    {
        float mx = -1e30f;
        #pragma unroll
        for (int k = 0; k < 8; k++) mx = fmaxf(mx, ss[warp*JB + lane + k*32]);
        #pragma unroll
        for (int o = 16; o > 0; o >>= 1) mx = fmaxf(mx, __shfl_xor_sync(0xffffffffu, mx, o));
        const float L2E = 1.4426950408889634f;
        float sum = 0.f;
        #pragma unroll
        for (int k = 0; k < 8; k++){
            float e = ex2a((ss[warp*JB + lane + k*32] - mx) * L2E);
            ss[warp*JB + lane + k*32] = e;
            attn[(b*LL + i0 + warp)*LL + j0g + lane + k*32] = e;   // unnormalized p
            sum += e;
        }
        #pragma unroll
        for (int o = 16; o > 0; o >>= 1) sum += __shfl_xor_sync(0xffffffffu, sum, o);
        if (lane == 0)
            g_stats[(b*LL + i0 + warp)*2 + jh] = make_float2(mx, sum);
    }
    CPWAIT0();
    __syncthreads();

    // ---------------- partial bmm: outpart[i][d] = sum_{j in half} p_ij * inp[j][d] ----------------
    const int d = tid;   // 0..127
    float a0 = 0.f, a1 = 0.f, a2 = 0.f, a3 = 0.f;
    #pragma unroll 1
    for (int ch = 0; ch < NCH; ch++){
        const int cur = ch & 1;
        if (ch < NCH-1){
            const float* src = &gI[(ch+1)*CH*128];
            #pragma unroll
            for (int t = 0; t < 4; t++)
                CPASYNC16(s2u(&sE[cur^1][(sr + t*4)*132 + sc]), &src[(sr + t*4)*128 + sc]);
            CPCOMMIT();
        }
        const int jc = ch * CH;
        #pragma unroll
        for (int jq = 0; jq < 4; jq++){
            float4 p0 = *(const float4*)&ss[0*JB + jc + jq*4];
            float4 p1 = *(const float4*)&ss[1*JB + jc + jq*4];
            float4 p2 = *(const float4*)&ss[2*JB + jc + jq*4];
            float4 p3 = *(const float4*)&ss[3*JB + jc + jq*4];
            const float* vb = &sE[cur][(jq*4)*132 + d];
            float v0 = vb[0*132], v1 = vb[1*132], v2 = vb[2*132], v3 = vb[3*132];
            a0 = fmaf(p0.x, v0, a0); a1 = fmaf(p1.x, v0, a1); a2 = fmaf(p2.x, v0, a2); a3 = fmaf(p3.x, v0, a3);
            a0 = fmaf(p0.y, v1, a0); a1 = fmaf(p1.y, v1, a1); a2 = fmaf(p2.y, v1, a2); a3 = fmaf(p3.y, v1, a3);
            a0 = fmaf(p0.z, v2, a0); a1 = fmaf(p1.z, v2, a1); a2 = fmaf(p2.z, v2, a2); a3 = fmaf(p3.z, v2, a3);
            a0 = fmaf(p0.w, v3, a0); a1 = fmaf(p1.w, v3, a1); a2 = fmaf(p2.w, v3, a2); a3 = fmaf(p3.w, v3, a3);
        }
        if (ch < NCH-1) CPWAIT0();
        __syncthreads();
    }
    g_outpart[((b*LL + i0 + 0)*2 + jh)*128 + d] = a0;
    g_outpart[((b*LL + i0 + 1)*2 + jh)*128 + d] = a1;
    g_outpart[((b*LL + i0 + 2)*2 + jh)*128 + d] = a2;
    g_outpart[((b*LL + i0 + 3)*2 + jh)*128 + d] = a3;
}

// ---------------------------------------------------------------------------
// Kernel C (merge): combine the two j-halves per row. grid BL=2048, block 128.
// out = (op0*c0 + op1*c1)/S ; attn[j in half h] *= c_h/S ; c_h = e^{m_h - M}.
// ---------------------------------------------------------------------------
__global__ __launch_bounds__(128) void merge_kernel(float* __restrict__ out,
                                                    float* __restrict__ attn){
    const int row = blockIdx.x;
    const int d   = threadIdx.x;
    float2 st0 = g_stats[row*2 + 0];
    float2 st1 = g_stats[row*2 + 1];
    const float L2E = 1.4426950408889634f;
    float M  = fmaxf(st0.x, st1.x);
    float c0 = ex2a((st0.x - M) * L2E);
    float c1 = ex2a((st1.x - M) * L2E);
    float S  = st0.y*c0 + st1.y*c1;
    float inv = 1.0f / S;
    out[row*128 + d] = (g_outpart[(row*2 + 0)*128 + d]*c0
                      + g_outpart[(row*2 + 1)*128 + d]*c1) * inv;
    float f0 = c0*inv, f1 = c1*inv;
    #pragma unroll
    for (int k = 0; k < 4; k++){
        int j = d + k*128;
        attn[row*512 + j] *= (k < 2) ? f0 : f1;
    }
}

// ---------------------------------------------------------------------------
extern "C" void kernel_launch(void* const* d_in, const int* in_sizes, int n_in,
                              void* d_out, int out_size){
    const float* inp = (const float*)d_in[0];
    const float* Wu  = (const float*)d_in[1];
    const float* Ww  = (const float*)d_in[2];
    const float* Wv  = (const float*)d_in[3];
    float* out = (float*)d_out;

    float* attn;
    if (out_size >= BB*LL*DD + BB*LL*LL){
        attn = out + BB*LL*DD;               // tuple layout: [out | attn]
    } else {
        void* p = nullptr;
        cudaGetSymbolAddress(&p, g_attn_scratch);
        attn = (float*)p;
    }

    proj_kernel <<<dim3(BL/PR, 2), 256>>>(inp, Wu, Ww);
    attnA_kernel<<<BL/TI*2, 128>>>(inp, Wv, attn);
    merge_kernel<<<BL, 128>>>(out, attn);
}